// round 14
// baseline (speedup 1.0000x reference)
#include <cuda_runtime.h>
#include <cuda_bf16.h>
#include <cstdint>
#include <cstddef>

#define NMAX 100000
#define EMAX 1600000
#define BKT  64   // per-node bucket capacity; deg ~ Poisson(16), P(>=64) ~ 1e-56

// ---------------- static device scratch (no runtime allocation) ----------------
__device__ int    g_is32;               // 1 if edge_index is int32, 0 if int64
__device__ int    g_deg[NMAX];
__device__ int    g_bkt[(size_t)NMAX * BKT];
__device__ float  g_A1[128 * 8];               // W1-projected attention vectors (s0..s3,d0..d3)
__device__ float  g_h1 [(size_t)NMAX * 128];   // layer1 pre-activation (fp32)
__device__ __align__(16) __nv_bfloat16 g_h1b[(size_t)NMAX * 128]; // bf16 copy, natural layout
__device__ float  g_h1a[(size_t)NMAX * 128];   // layer1 output (post ELU)
__device__ float  g_h2 [(size_t)NMAX * 32];    // layer2 features (fp32)
__device__ float4 g_al1s[NMAX];                // layer1 src logits (4 heads)
__device__ float4 g_al1d[NMAX];                // layer1 dst logits (4 heads)
__device__ float  g_al2s[NMAX];
__device__ float  g_al2d[NMAX];
__device__ float  g_pool[32];

__device__ __forceinline__ float lrelu(float v) { return v > 0.f ? v : 0.2f * v; }

__device__ __forceinline__ unsigned f2tf32(float x) {
    unsigned r;
    asm("cvt.rna.tf32.f32 %0, %1;" : "=r"(r) : "f"(x));
    return r;
}

// ---------------- init + dtype probe (merged) ----------------
__global__ void k_init(const unsigned long long* __restrict__ ei, int E, int n) {
    int i = blockIdx.x * blockDim.x + threadIdx.x;
    if (i < n) g_deg[i] = 0;
    if (i < 32) g_pool[i] = 0.f;
    if (blockIdx.x == 0) {
        __shared__ int sbad;
        if (threadIdx.x == 0) sbad = 0;
        __syncthreads();
        int bad = 0;
        int lim = (E < 2048) ? E : 2048;
        for (int j = threadIdx.x; j < lim; j += blockDim.x) {
            unsigned long long v = ei[j];
            if (v >= (unsigned long long)n) bad = 1;
        }
        if (bad) atomicOr(&sbad, 1);
        __syncthreads();
        if (threadIdx.x == 0) g_is32 = sbad;
    }
}

// ---------------- bucket fill ----------------
__global__ void k_fill(const void* __restrict__ ei, int E) {
    int i = blockIdx.x * blockDim.x + threadIdx.x;
    if (i >= E) return;
    int s, d;
    if (g_is32) {
        const int* p = (const int*)ei;
        s = p[i];
        d = p[E + i];
    } else {
        const long long* p = (const long long*)ei;
        s = (int)p[i];
        d = (int)p[(size_t)E + i];
    }
    int pos = atomicAdd(&g_deg[d], 1);
    if (pos < BKT) g_bkt[(size_t)d * BKT + pos] = s;
}

// ---------------- prep: A1[k][j] = sum_c W1[k][j*32+c]*a_s[j][c] (j<4), a_d (j>=4) ----------------
__global__ void k_prep(const float* __restrict__ W1,
                       const float* __restrict__ a_s, const float* __restrict__ a_d) {
    int k = threadIdx.x;   // 128 threads
    float acc[8];
#pragma unroll
    for (int j = 0; j < 8; j++) acc[j] = 0.f;
    for (int c = 0; c < 32; c++) {
#pragma unroll
        for (int j = 0; j < 4; j++) {
            float w = W1[k * 128 + j * 32 + c];
            acc[j]     = fmaf(w, a_s[j * 32 + c], acc[j]);
            acc[4 + j] = fmaf(w, a_d[j * 32 + c], acc[4 + j]);
        }
    }
#pragma unroll
    for (int j = 0; j < 8; j++) g_A1[k * 8 + j] = acc[j];
}

// ---------------- GEMM1 (tf32) + fused logits + bf16 copy ----------------
__global__ void __launch_bounds__(256) k_gemm1(const float* __restrict__ A,
                                               const float* __restrict__ B, int n) {
    __shared__ __align__(16) float As[128][68];
    __shared__ __align__(16) float Bs[64][132];
    __shared__ __align__(16) float A1s[64][9];
    int tid = threadIdx.x;
    int lane = tid & 31;
    int warp = tid >> 5;
    int warpM = warp & 3;
    int warpN = warp >> 2;
    int g = lane >> 2;
    int t = lane & 3;
    int m0 = blockIdx.x * 128;

    float c[2][8][4];
#pragma unroll
    for (int mt = 0; mt < 2; mt++)
#pragma unroll
        for (int nt = 0; nt < 8; nt++)
#pragma unroll
            for (int q = 0; q < 4; q++) c[mt][nt][q] = 0.f;

    float cL[2][4];   // logits accumulators (warpN==0 only)
#pragma unroll
    for (int mt = 0; mt < 2; mt++)
#pragma unroll
        for (int q = 0; q < 4; q++) cL[mt][q] = 0.f;

    for (int k0 = 0; k0 < 128; k0 += 64) {
        {
            int r = tid >> 4;
            int c4 = (tid & 15) * 4;
#pragma unroll
            for (int p = 0; p < 8; p++) {
                int row = r + p * 16;
                int grow = m0 + row;
                float4 v = make_float4(0.f, 0.f, 0.f, 0.f);
                if (grow < n) v = *(const float4*)(A + (size_t)grow * 128 + k0 + c4);
                As[row][c4 + 0] = __uint_as_float(f2tf32(v.x));
                As[row][c4 + 1] = __uint_as_float(f2tf32(v.y));
                As[row][c4 + 2] = __uint_as_float(f2tf32(v.z));
                As[row][c4 + 3] = __uint_as_float(f2tf32(v.w));
            }
        }
        {
            int r = tid >> 5;
            int c4 = (tid & 31) * 4;
#pragma unroll
            for (int p = 0; p < 8; p++) {
                int k = r + p * 8;
                float4 v = *(const float4*)(B + (size_t)(k0 + k) * 128 + c4);
                Bs[k][c4 + 0] = __uint_as_float(f2tf32(v.x));
                Bs[k][c4 + 1] = __uint_as_float(f2tf32(v.y));
                Bs[k][c4 + 2] = __uint_as_float(f2tf32(v.z));
                Bs[k][c4 + 3] = __uint_as_float(f2tf32(v.w));
            }
        }
        // A1 tile: 64 x 8
        {
#pragma unroll
            for (int p = 0; p < 2; p++) {
                int idx = tid + p * 256;
                if (idx < 512) {
                    int k = idx >> 3, j = idx & 7;
                    A1s[k][j] = __uint_as_float(f2tf32(g_A1[(k0 + k) * 8 + j]));
                }
            }
        }
        __syncthreads();

#pragma unroll
        for (int ks = 0; ks < 8; ks++) {
            int kk = ks * 8;
            unsigned a[2][4];
#pragma unroll
            for (int mt = 0; mt < 2; mt++) {
                int r = warpM * 32 + mt * 16 + g;
                a[mt][0] = __float_as_uint(As[r    ][kk + t    ]);
                a[mt][1] = __float_as_uint(As[r + 8][kk + t    ]);
                a[mt][2] = __float_as_uint(As[r    ][kk + t + 4]);
                a[mt][3] = __float_as_uint(As[r + 8][kk + t + 4]);
            }
            unsigned b[8][2];
#pragma unroll
            for (int nt = 0; nt < 8; nt++) {
                int cN = warpN * 64 + nt * 8 + g;
                b[nt][0] = __float_as_uint(Bs[kk + t    ][cN]);
                b[nt][1] = __float_as_uint(Bs[kk + t + 4][cN]);
            }
#pragma unroll
            for (int mt = 0; mt < 2; mt++)
#pragma unroll
                for (int nt = 0; nt < 8; nt++) {
                    asm volatile(
                        "mma.sync.aligned.m16n8k8.row.col.f32.tf32.tf32.f32 "
                        "{%0,%1,%2,%3}, {%4,%5,%6,%7}, {%8,%9}, {%0,%1,%2,%3};"
                        : "+f"(c[mt][nt][0]), "+f"(c[mt][nt][1]),
                          "+f"(c[mt][nt][2]), "+f"(c[mt][nt][3])
                        : "r"(a[mt][0]), "r"(a[mt][1]), "r"(a[mt][2]), "r"(a[mt][3]),
                          "r"(b[nt][0]), "r"(b[nt][1]));
                }
            if (warpN == 0) {
                unsigned bl0 = __float_as_uint(A1s[kk + t    ][g]);
                unsigned bl1 = __float_as_uint(A1s[kk + t + 4][g]);
#pragma unroll
                for (int mt = 0; mt < 2; mt++) {
                    asm volatile(
                        "mma.sync.aligned.m16n8k8.row.col.f32.tf32.tf32.f32 "
                        "{%0,%1,%2,%3}, {%4,%5,%6,%7}, {%8,%9}, {%0,%1,%2,%3};"
                        : "+f"(cL[mt][0]), "+f"(cL[mt][1]),
                          "+f"(cL[mt][2]), "+f"(cL[mt][3])
                        : "r"(a[mt][0]), "r"(a[mt][1]), "r"(a[mt][2]), "r"(a[mt][3]),
                          "r"(bl0), "r"(bl1));
                }
            }
        }
        __syncthreads();
    }

    // epilogue: h1 fp32 + h1b bf16 (natural layout) + logits (warpN==0)
#pragma unroll
    for (int mt = 0; mt < 2; mt++) {
        int row = m0 + warpM * 32 + mt * 16 + g;
#pragma unroll
        for (int nt = 0; nt < 8; nt++) {
            int col = warpN * 64 + nt * 8 + t * 2;
            if (row < n) {
                *(float2*)&g_h1[(size_t)row * 128 + col] = make_float2(c[mt][nt][0], c[mt][nt][1]);
                *(__nv_bfloat162*)&g_h1b[(size_t)row * 128 + col] =
                    __floats2bfloat162_rn(c[mt][nt][0], c[mt][nt][1]);
            }
            if (row + 8 < n) {
                *(float2*)&g_h1[(size_t)(row + 8) * 128 + col] = make_float2(c[mt][nt][2], c[mt][nt][3]);
                *(__nv_bfloat162*)&g_h1b[(size_t)(row + 8) * 128 + col] =
                    __floats2bfloat162_rn(c[mt][nt][2], c[mt][nt][3]);
            }
        }
    }
    if (warpN == 0) {
#pragma unroll
        for (int mt = 0; mt < 2; mt++) {
            int row = m0 + warpM * 32 + mt * 16 + g;
            float v0 = cL[mt][0], v1 = cL[mt][1];   // cols 2t, 2t+1 (row)
            float u0 = cL[mt][2], u1 = cL[mt][3];   // cols 2t, 2t+1 (row+8)
            float v2 = __shfl_down_sync(0xffffffffu, v0, 1);
            float v3 = __shfl_down_sync(0xffffffffu, v1, 1);
            float u2 = __shfl_down_sync(0xffffffffu, u0, 1);
            float u3 = __shfl_down_sync(0xffffffffu, u1, 1);
            if (t == 0) {
                if (row < n)     g_al1s[row]     = make_float4(v0, v1, v2, v3);
                if (row + 8 < n) g_al1s[row + 8] = make_float4(u0, u1, u2, u3);
            }
            if (t == 2) {
                if (row < n)     g_al1d[row]     = make_float4(v0, v1, v2, v3);
                if (row + 8 < n) g_al1d[row + 8] = make_float4(u0, u1, u2, u3);
            }
        }
    }
}

// ---------------- layer-1 fused aggregation (bf16 natural-layout gather) ----------------
// lane owns 4 consecutive channels of one head: cols 4*lane .. 4*lane+3, head = lane>>3
__global__ void __launch_bounds__(256) k_agg1(const float* __restrict__ b1, int n) {
    __shared__ __align__(16) float4 s_w[8][32];
    __shared__ int s_src[8][32];
    int lane = threadIdx.x & 31;
    int wib = threadIdx.x >> 5;
    int node = blockIdx.x * 8 + wib;
    if (node >= n) return;
    int head = lane >> 3;
    int degn = g_deg[node]; if (degn > BKT) degn = BKT;
    const int* bkt = g_bkt + (size_t)node * BKT;

    float4 alD = g_al1d[node];
    float4 alS = g_al1s[node];

    float w0 = __expf(lrelu(alS.x + alD.x));
    float w1 = __expf(lrelu(alS.y + alD.y));
    float w2 = __expf(lrelu(alS.z + alD.z));
    float w3 = __expf(lrelu(alS.w + alD.w));
    float t0 = (lane == 0) ? w0 : 0.f, t1 = (lane == 0) ? w1 : 0.f;
    float t2 = (lane == 0) ? w2 : 0.f, t3 = (lane == 0) ? w3 : 0.f;
    float wself = (head == 0) ? w0 : (head == 1) ? w1 : (head == 2) ? w2 : w3;

    float4 hv = *(const float4*)&g_h1[(size_t)node * 128 + 4 * lane];
    float acc0 = hv.x * wself;
    float acc1 = hv.y * wself;
    float acc2 = hv.z * wself;
    float acc3 = hv.w * wself;

    const __nv_bfloat16* __restrict__ hp1 = g_h1b;

    for (int chunk = 0; chunk < degn; chunk += 32) {
        int i = chunk + lane;
        float4 w = make_float4(0.f, 0.f, 0.f, 0.f);
        int s = 0;
        if (i < degn) {
            s = __ldg(&bkt[i]);
            float4 a = __ldg(&g_al1s[s]);
            w.x = __expf(lrelu(a.x + alD.x));
            w.y = __expf(lrelu(a.y + alD.y));
            w.z = __expf(lrelu(a.z + alD.z));
            w.w = __expf(lrelu(a.w + alD.w));
            t0 += w.x; t1 += w.y; t2 += w.z; t3 += w.w;
        }
        s_src[wib][lane] = s;
        s_w[wib][lane] = w;
        __syncwarp(0xffffffffu);
        int cnt = degn - chunk; if (cnt > 32) cnt = 32;
        int j = 0;
        for (; j + 4 <= cnt; j += 4) {
            int sa = s_src[wib][j    ];
            int sb = s_src[wib][j + 1];
            int sc = s_src[wib][j + 2];
            int sd = s_src[wib][j + 3];
            uint2 ua = __ldg((const uint2*)(hp1 + (size_t)sa * 128 + 4 * lane));
            uint2 ub = __ldg((const uint2*)(hp1 + (size_t)sb * 128 + 4 * lane));
            uint2 uc = __ldg((const uint2*)(hp1 + (size_t)sc * 128 + 4 * lane));
            uint2 ud = __ldg((const uint2*)(hp1 + (size_t)sd * 128 + 4 * lane));
            float4 wa = s_w[wib][j    ];
            float4 wb = s_w[wib][j + 1];
            float4 wc = s_w[wib][j + 2];
            float4 wd = s_w[wib][j + 3];
            float wsa = (head == 0) ? wa.x : (head == 1) ? wa.y : (head == 2) ? wa.z : wa.w;
            float wsb = (head == 0) ? wb.x : (head == 1) ? wb.y : (head == 2) ? wb.z : wb.w;
            float wsc = (head == 0) ? wc.x : (head == 1) ? wc.y : (head == 2) ? wc.z : wc.w;
            float wsd = (head == 0) ? wd.x : (head == 1) ? wd.y : (head == 2) ? wd.z : wd.w;
            float2 fa01 = __bfloat1622float2(*(const __nv_bfloat162*)&ua.x);
            float2 fa23 = __bfloat1622float2(*(const __nv_bfloat162*)&ua.y);
            float2 fb01 = __bfloat1622float2(*(const __nv_bfloat162*)&ub.x);
            float2 fb23 = __bfloat1622float2(*(const __nv_bfloat162*)&ub.y);
            float2 fc01 = __bfloat1622float2(*(const __nv_bfloat162*)&uc.x);
            float2 fc23 = __bfloat1622float2(*(const __nv_bfloat162*)&uc.y);
            float2 fd01 = __bfloat1622float2(*(const __nv_bfloat162*)&ud.x);
            float2 fd23 = __bfloat1622float2(*(const __nv_bfloat162*)&ud.y);
            acc0 = fmaf(fa01.x, wsa, acc0); acc1 = fmaf(fa01.y, wsa, acc1);
            acc2 = fmaf(fa23.x, wsa, acc2); acc3 = fmaf(fa23.y, wsa, acc3);
            acc0 = fmaf(fb01.x, wsb, acc0); acc1 = fmaf(fb01.y, wsb, acc1);
            acc2 = fmaf(fb23.x, wsb, acc2); acc3 = fmaf(fb23.y, wsb, acc3);
            acc0 = fmaf(fc01.x, wsc, acc0); acc1 = fmaf(fc01.y, wsc, acc1);
            acc2 = fmaf(fc23.x, wsc, acc2); acc3 = fmaf(fc23.y, wsc, acc3);
            acc0 = fmaf(fd01.x, wsd, acc0); acc1 = fmaf(fd01.y, wsd, acc1);
            acc2 = fmaf(fd23.x, wsd, acc2); acc3 = fmaf(fd23.y, wsd, acc3);
        }
        for (; j < cnt; j++) {
            int sj = s_src[wib][j];
            float4 wj = s_w[wib][j];
            float ws = (head == 0) ? wj.x : (head == 1) ? wj.y : (head == 2) ? wj.z : wj.w;
            uint2 u = __ldg((const uint2*)(hp1 + (size_t)sj * 128 + 4 * lane));
            float2 f01 = __bfloat1622float2(*(const __nv_bfloat162*)&u.x);
            float2 f23 = __bfloat1622float2(*(const __nv_bfloat162*)&u.y);
            acc0 = fmaf(f01.x, ws, acc0);
            acc1 = fmaf(f01.y, ws, acc1);
            acc2 = fmaf(f23.x, ws, acc2);
            acc3 = fmaf(f23.y, ws, acc3);
        }
        __syncwarp(0xffffffffu);
    }

#pragma unroll
    for (int o = 16; o > 0; o >>= 1) {
        t0 += __shfl_xor_sync(0xffffffffu, t0, o);
        t1 += __shfl_xor_sync(0xffffffffu, t1, o);
        t2 += __shfl_xor_sync(0xffffffffu, t2, o);
        t3 += __shfl_xor_sync(0xffffffffu, t3, o);
    }
    float tsel = (head == 0) ? t0 : (head == 1) ? t1 : (head == 2) ? t2 : t3;
    float inv = 1.f / tsel;
    float4 b1v = *(const float4*)&b1[4 * lane];
    float v0 = acc0 * inv + b1v.x;
    float v1 = acc1 * inv + b1v.y;
    float v2 = acc2 * inv + b1v.z;
    float v3 = acc3 * inv + b1v.w;
    float4 outv;
    outv.x = v0 > 0.f ? v0 : (__expf(v0) - 1.f);
    outv.y = v1 > 0.f ? v1 : (__expf(v1) - 1.f);
    outv.z = v2 > 0.f ? v2 : (__expf(v2) - 1.f);
    outv.w = v3 > 0.f ? v3 : (__expf(v3) - 1.f);
    *(float4*)&g_h1a[(size_t)node * 128 + 4 * lane] = outv;
}

// ---------------- GEMM2 (tf32) + fused layer-2 logits ----------------
__global__ void __launch_bounds__(256) k_gemm2(const float* __restrict__ B,
                                               const float* __restrict__ a_s,
                                               const float* __restrict__ a_d, int n) {
    __shared__ __align__(16) float As[128][68];
    __shared__ __align__(16) float Bs[64][36];
    int tid = threadIdx.x;
    int lane = tid & 31;
    int warp = tid >> 5;
    int g = lane >> 2;
    int t = lane & 3;
    int m0 = blockIdx.x * 128;

    float c[4][4];
#pragma unroll
    for (int nt = 0; nt < 4; nt++)
#pragma unroll
        for (int q = 0; q < 4; q++) c[nt][q] = 0.f;

    for (int k0 = 0; k0 < 128; k0 += 64) {
        {
            int r = tid >> 4;
            int c4 = (tid & 15) * 4;
#pragma unroll
            for (int p = 0; p < 8; p++) {
                int row = r + p * 16;
                int grow = m0 + row;
                float4 v = make_float4(0.f, 0.f, 0.f, 0.f);
                if (grow < n) v = *(const float4*)&g_h1a[(size_t)grow * 128 + k0 + c4];
                As[row][c4 + 0] = __uint_as_float(f2tf32(v.x));
                As[row][c4 + 1] = __uint_as_float(f2tf32(v.y));
                As[row][c4 + 2] = __uint_as_float(f2tf32(v.z));
                As[row][c4 + 3] = __uint_as_float(f2tf32(v.w));
            }
        }
        {
            int r = tid >> 3;
            int c4 = (tid & 7) * 4;
#pragma unroll
            for (int p = 0; p < 2; p++) {
                int k = r + p * 32;
                float4 v = *(const float4*)(B + (size_t)(k0 + k) * 32 + c4);
                Bs[k][c4 + 0] = __uint_as_float(f2tf32(v.x));
                Bs[k][c4 + 1] = __uint_as_float(f2tf32(v.y));
                Bs[k][c4 + 2] = __uint_as_float(f2tf32(v.z));
                Bs[k][c4 + 3] = __uint_as_float(f2tf32(v.w));
            }
        }
        __syncthreads();

#pragma unroll
        for (int ks = 0; ks < 8; ks++) {
            int kk = ks * 8;
            int r = warp * 16 + g;
            unsigned a0 = __float_as_uint(As[r    ][kk + t    ]);
            unsigned a1 = __float_as_uint(As[r + 8][kk + t    ]);
            unsigned a2 = __float_as_uint(As[r    ][kk + t + 4]);
            unsigned a3 = __float_as_uint(As[r + 8][kk + t + 4]);
#pragma unroll
            for (int nt = 0; nt < 4; nt++) {
                int cN = nt * 8 + g;
                unsigned b0 = __float_as_uint(Bs[kk + t    ][cN]);
                unsigned b1 = __float_as_uint(Bs[kk + t + 4][cN]);
                asm volatile(
                    "mma.sync.aligned.m16n8k8.row.col.f32.tf32.tf32.f32 "
                    "{%0,%1,%2,%3}, {%4,%5,%6,%7}, {%8,%9}, {%0,%1,%2,%3};"
                    : "+f"(c[nt][0]), "+f"(c[nt][1]), "+f"(c[nt][2]), "+f"(c[nt][3])
                    : "r"(a0), "r"(a1), "r"(a2), "r"(a3), "r"(b0), "r"(b1));
            }
        }
        __syncthreads();
    }

    int row = m0 + warp * 16 + g;
    float s_lo = 0.f, d_lo = 0.f, s_hi = 0.f, d_hi = 0.f;
#pragma unroll
    for (int nt = 0; nt < 4; nt++) {
        int col = nt * 8 + t * 2;
        float as0 = a_s[col], as1 = a_s[col + 1];
        float ad0 = a_d[col], ad1 = a_d[col + 1];
        s_lo = fmaf(c[nt][0], as0, fmaf(c[nt][1], as1, s_lo));
        d_lo = fmaf(c[nt][0], ad0, fmaf(c[nt][1], ad1, d_lo));
        s_hi = fmaf(c[nt][2], as0, fmaf(c[nt][3], as1, s_hi));
        d_hi = fmaf(c[nt][2], ad0, fmaf(c[nt][3], ad1, d_hi));
        if (row < n)
            *(float2*)&g_h2[(size_t)row * 32 + col] = make_float2(c[nt][0], c[nt][1]);
        if (row + 8 < n)
            *(float2*)&g_h2[(size_t)(row + 8) * 32 + col] = make_float2(c[nt][2], c[nt][3]);
    }
#pragma unroll
    for (int o = 1; o <= 2; o <<= 1) {
        s_lo += __shfl_xor_sync(0xffffffffu, s_lo, o);
        d_lo += __shfl_xor_sync(0xffffffffu, d_lo, o);
        s_hi += __shfl_xor_sync(0xffffffffu, s_hi, o);
        d_hi += __shfl_xor_sync(0xffffffffu, d_hi, o);
    }
    if (t == 0) {
        if (row < n)     { g_al2s[row]     = s_lo; g_al2d[row]     = d_lo; }
        if (row + 8 < n) { g_al2s[row + 8] = s_hi; g_al2d[row + 8] = d_hi; }
    }
}

// ---------------- layer-2 aggregation (fp32 gather from buckets) + mean-pool partial ----------------
__global__ void __launch_bounds__(256) k_agg2(int n) {
    __shared__ __align__(16) float s_w2[8][32];
    __shared__ int s_src2[8][32];
    __shared__ __align__(16) float bacc[8][32];
    int tid = threadIdx.x;
    int lane = tid & 31;
    int wib = tid >> 5;
    int node = blockIdx.x * 8 + wib;

    float acc = 0.f;
    if (node < n) {
        int degn = g_deg[node]; if (degn > BKT) degn = BKT;
        const int* bkt = g_bkt + (size_t)node * BKT;
        float alD = g_al2d[node];
        float ws = __expf(lrelu(g_al2s[node] + alD));
        float t = (lane == 0) ? ws : 0.f;
        acc = g_h2[(size_t)node * 32 + lane] * ws;

        for (int chunk = 0; chunk < degn; chunk += 32) {
            int i = chunk + lane;
            float w = 0.f;
            int s = 0;
            if (i < degn) {
                s = __ldg(&bkt[i]);
                w = __expf(lrelu(__ldg(&g_al2s[s]) + alD));
                t += w;
            }
            s_src2[wib][lane] = s;
            s_w2[wib][lane] = w;
            __syncwarp(0xffffffffu);
            int cnt = degn - chunk; if (cnt > 32) cnt = 32;
#pragma unroll 2
            for (int j = 0; j < cnt; j++) {
                int sj = s_src2[wib][j];
                float wj = s_w2[wib][j];
                acc = fmaf(__ldg(&g_h2[(size_t)sj * 32 + lane]), wj, acc);
            }
            __syncwarp(0xffffffffu);
        }
#pragma unroll
        for (int o = 16; o > 0; o >>= 1) t += __shfl_xor_sync(0xffffffffu, t, o);
        acc *= (1.f / t);
    }
    bacc[wib][lane] = acc;
    __syncthreads();
    if (tid < 32) {
        float s = 0.f;
#pragma unroll
        for (int w = 0; w < 8; w++) s += bacc[w][tid];
        atomicAdd(&g_pool[tid], s);
    }
}

// ---------------- final: pooled mean -> linear -> softmax ----------------
__global__ void k_final(const float* __restrict__ linW, const float* __restrict__ linb,
                        const float* __restrict__ b2, float* __restrict__ out, int n) {
    if (threadIdx.x == 0) {
        float p[32];
        float invn = 1.f / (float)n;
        for (int c = 0; c < 32; c++) p[c] = g_pool[c] * invn + b2[c];
        float lg[3];
        for (int j = 0; j < 3; j++) lg[j] = linb[j];
        for (int c = 0; c < 32; c++)
            for (int j = 0; j < 3; j++) lg[j] += p[c] * linW[c * 3 + j];
        float mx = fmaxf(lg[0], fmaxf(lg[1], lg[2]));
        float e0 = expf(lg[0] - mx), e1 = expf(lg[1] - mx), e2 = expf(lg[2] - mx);
        float s = e0 + e1 + e2;
        out[0] = e0 / s; out[1] = e1 / s; out[2] = e2 / s;
    }
}

// ---------------- launcher (bucket build forked onto a side stream) ----------------
static cudaStream_t g_s2 = nullptr;
static cudaEvent_t  g_evFork = nullptr, g_evJoin = nullptr;

extern "C" void kernel_launch(void* const* d_in, const int* in_sizes, int n_in,
                              void* d_out, int out_size) {
    const float* x    = (const float*)d_in[0];
    const void*  ei   = d_in[1];
    const float* W1   = (const float*)d_in[2];
    const float* a1s  = (const float*)d_in[3];
    const float* a1d  = (const float*)d_in[4];
    const float* b1   = (const float*)d_in[5];
    const float* W2   = (const float*)d_in[6];
    const float* a2s  = (const float*)d_in[7];
    const float* a2d  = (const float*)d_in[8];
    const float* b2   = (const float*)d_in[9];
    const float* linW = (const float*)d_in[10];
    const float* linb = (const float*)d_in[11];
    float*       out  = (float*)d_out;

    int n = in_sizes[0] / 128;       // 100000
    int E = in_sizes[1] / 2;         // 1600000
    if (n > NMAX) n = NMAX;
    if (E > EMAX) E = EMAX;

    if (!g_s2) {
        cudaStreamCreateWithFlags(&g_s2, cudaStreamNonBlocking);
        cudaEventCreateWithFlags(&g_evFork, cudaEventDisableTiming);
        cudaEventCreateWithFlags(&g_evJoin, cudaEventDisableTiming);
    }

    // fork: bucket build on side stream, concurrent with prep+gemm1 on main stream
    cudaEventRecord(g_evFork, 0);
    cudaStreamWaitEvent(g_s2, g_evFork, 0);

    k_init <<<(n + 255) / 256, 256, 0, g_s2>>>((const unsigned long long*)ei, E, n);
    k_fill <<<(E + 255) / 256, 256, 0, g_s2>>>(ei, E);
    cudaEventRecord(g_evJoin, g_s2);

    k_prep <<<1, 128>>>(W1, a1s, a1d);
    k_gemm1<<<(n + 127) / 128, 256>>>(x, W1, n);

    // join: agg1 needs buckets + logits + h1b
    cudaStreamWaitEvent(0, g_evJoin, 0);

    k_agg1 <<<(n + 7) / 8, 256>>>(b1, n);
    k_gemm2<<<(n + 127) / 128, 256>>>(W2, a2s, a2d, n);
    k_agg2 <<<(n + 7) / 8, 256>>>(n);
    k_final<<<1, 32>>>(linW, linb, b2, out, n);
}

// round 15
// speedup vs baseline: 1.1256x; 1.1256x over previous
#include <cuda_runtime.h>
#include <cuda_bf16.h>
#include <cstdint>
#include <cstddef>

#define NMAX 100000
#define EMAX 1600000
#define BKT  64   // per-node bucket capacity; deg ~ Poisson(16), P(>=64) ~ 1e-56

// ---------------- static device scratch (no runtime allocation) ----------------
__device__ int    g_is32;               // 1 if edge_index is int32, 0 if int64
__device__ int    g_deg[NMAX];
__device__ int    g_bkt[(size_t)NMAX * BKT];
__device__ float  g_A1[128 * 8];               // W1-projected attention vectors (s0..s3,d0..d3)
__device__ __align__(16) __nv_bfloat16 g_h1b[(size_t)NMAX * 128]; // layer1 features, bf16
__device__ float  g_h1a[(size_t)NMAX * 128];   // layer1 output (post ELU)
__device__ float  g_h2 [(size_t)NMAX * 32];    // layer2 features (fp32)
__device__ float4 g_al1s[NMAX];                // layer1 src logits (4 heads)
__device__ float4 g_al1d[NMAX];                // layer1 dst logits (4 heads)
__device__ float  g_al2s[NMAX];
__device__ float  g_al2d[NMAX];
__device__ float  g_pool[32];

__device__ __forceinline__ float lrelu(float v) { return v > 0.f ? v : 0.2f * v; }

__device__ __forceinline__ unsigned f2tf32(float x) {
    unsigned r;
    asm("cvt.rna.tf32.f32 %0, %1;" : "=r"(r) : "f"(x));
    return r;
}

// ---------------- init + dtype probe (merged) ----------------
__global__ void k_init(const unsigned long long* __restrict__ ei, int E, int n) {
    int i = blockIdx.x * blockDim.x + threadIdx.x;
    if (i < n) g_deg[i] = 0;
    if (i < 32) g_pool[i] = 0.f;
    if (blockIdx.x == 0) {
        __shared__ int sbad;
        if (threadIdx.x == 0) sbad = 0;
        __syncthreads();
        int bad = 0;
        int lim = (E < 2048) ? E : 2048;
        for (int j = threadIdx.x; j < lim; j += blockDim.x) {
            unsigned long long v = ei[j];
            if (v >= (unsigned long long)n) bad = 1;
        }
        if (bad) atomicOr(&sbad, 1);
        __syncthreads();
        if (threadIdx.x == 0) g_is32 = sbad;
    }
}

// ---------------- bucket fill ----------------
__global__ void k_fill(const void* __restrict__ ei, int E) {
    int i = blockIdx.x * blockDim.x + threadIdx.x;
    if (i >= E) return;
    int s, d;
    if (g_is32) {
        const int* p = (const int*)ei;
        s = p[i];
        d = p[E + i];
    } else {
        const long long* p = (const long long*)ei;
        s = (int)p[i];
        d = (int)p[(size_t)E + i];
    }
    int pos = atomicAdd(&g_deg[d], 1);
    if (pos < BKT) g_bkt[(size_t)d * BKT + pos] = s;
}

// ---------------- prep: A1[k][j] = sum_c W1[k][j*32+c]*a_s[j][c] (j<4), a_d (j>=4) ----------------
__global__ void k_prep(const float* __restrict__ W1,
                       const float* __restrict__ a_s, const float* __restrict__ a_d) {
    int k = threadIdx.x;   // 128 threads
    float acc[8];
#pragma unroll
    for (int j = 0; j < 8; j++) acc[j] = 0.f;
    for (int c = 0; c < 32; c++) {
#pragma unroll
        for (int j = 0; j < 4; j++) {
            float w = W1[k * 128 + j * 32 + c];
            acc[j]     = fmaf(w, a_s[j * 32 + c], acc[j]);
            acc[4 + j] = fmaf(w, a_d[j * 32 + c], acc[4 + j]);
        }
    }
#pragma unroll
    for (int j = 0; j < 8; j++) g_A1[k * 8 + j] = acc[j];
}

// ---------------- GEMM1 (tf32) + fused logits + bf16 output only ----------------
__global__ void __launch_bounds__(256) k_gemm1(const float* __restrict__ A,
                                               const float* __restrict__ B, int n) {
    __shared__ __align__(16) float As[128][68];
    __shared__ __align__(16) float Bs[64][132];
    __shared__ __align__(16) float A1s[64][9];
    int tid = threadIdx.x;
    int lane = tid & 31;
    int warp = tid >> 5;
    int warpM = warp & 3;
    int warpN = warp >> 2;
    int g = lane >> 2;
    int t = lane & 3;
    int m0 = blockIdx.x * 128;

    float c[2][8][4];
#pragma unroll
    for (int mt = 0; mt < 2; mt++)
#pragma unroll
        for (int nt = 0; nt < 8; nt++)
#pragma unroll
            for (int q = 0; q < 4; q++) c[mt][nt][q] = 0.f;

    float cL[2][4];   // logits accumulators (warpN==0 only)
#pragma unroll
    for (int mt = 0; mt < 2; mt++)
#pragma unroll
        for (int q = 0; q < 4; q++) cL[mt][q] = 0.f;

    for (int k0 = 0; k0 < 128; k0 += 64) {
        {
            int r = tid >> 4;
            int c4 = (tid & 15) * 4;
#pragma unroll
            for (int p = 0; p < 8; p++) {
                int row = r + p * 16;
                int grow = m0 + row;
                float4 v = make_float4(0.f, 0.f, 0.f, 0.f);
                if (grow < n) v = *(const float4*)(A + (size_t)grow * 128 + k0 + c4);
                As[row][c4 + 0] = __uint_as_float(f2tf32(v.x));
                As[row][c4 + 1] = __uint_as_float(f2tf32(v.y));
                As[row][c4 + 2] = __uint_as_float(f2tf32(v.z));
                As[row][c4 + 3] = __uint_as_float(f2tf32(v.w));
            }
        }
        {
            int r = tid >> 5;
            int c4 = (tid & 31) * 4;
#pragma unroll
            for (int p = 0; p < 8; p++) {
                int k = r + p * 8;
                float4 v = *(const float4*)(B + (size_t)(k0 + k) * 128 + c4);
                Bs[k][c4 + 0] = __uint_as_float(f2tf32(v.x));
                Bs[k][c4 + 1] = __uint_as_float(f2tf32(v.y));
                Bs[k][c4 + 2] = __uint_as_float(f2tf32(v.z));
                Bs[k][c4 + 3] = __uint_as_float(f2tf32(v.w));
            }
        }
        // A1 tile: 64 x 8
        {
#pragma unroll
            for (int p = 0; p < 2; p++) {
                int idx = tid + p * 256;
                if (idx < 512) {
                    int k = idx >> 3, j = idx & 7;
                    A1s[k][j] = __uint_as_float(f2tf32(g_A1[(k0 + k) * 8 + j]));
                }
            }
        }
        __syncthreads();

#pragma unroll
        for (int ks = 0; ks < 8; ks++) {
            int kk = ks * 8;
            unsigned a[2][4];
#pragma unroll
            for (int mt = 0; mt < 2; mt++) {
                int r = warpM * 32 + mt * 16 + g;
                a[mt][0] = __float_as_uint(As[r    ][kk + t    ]);
                a[mt][1] = __float_as_uint(As[r + 8][kk + t    ]);
                a[mt][2] = __float_as_uint(As[r    ][kk + t + 4]);
                a[mt][3] = __float_as_uint(As[r + 8][kk + t + 4]);
            }
            unsigned b[8][2];
#pragma unroll
            for (int nt = 0; nt < 8; nt++) {
                int cN = warpN * 64 + nt * 8 + g;
                b[nt][0] = __float_as_uint(Bs[kk + t    ][cN]);
                b[nt][1] = __float_as_uint(Bs[kk + t + 4][cN]);
            }
#pragma unroll
            for (int mt = 0; mt < 2; mt++)
#pragma unroll
                for (int nt = 0; nt < 8; nt++) {
                    asm volatile(
                        "mma.sync.aligned.m16n8k8.row.col.f32.tf32.tf32.f32 "
                        "{%0,%1,%2,%3}, {%4,%5,%6,%7}, {%8,%9}, {%0,%1,%2,%3};"
                        : "+f"(c[mt][nt][0]), "+f"(c[mt][nt][1]),
                          "+f"(c[mt][nt][2]), "+f"(c[mt][nt][3])
                        : "r"(a[mt][0]), "r"(a[mt][1]), "r"(a[mt][2]), "r"(a[mt][3]),
                          "r"(b[nt][0]), "r"(b[nt][1]));
                }
            if (warpN == 0) {
                unsigned bl0 = __float_as_uint(A1s[kk + t    ][g]);
                unsigned bl1 = __float_as_uint(A1s[kk + t + 4][g]);
#pragma unroll
                for (int mt = 0; mt < 2; mt++) {
                    asm volatile(
                        "mma.sync.aligned.m16n8k8.row.col.f32.tf32.tf32.f32 "
                        "{%0,%1,%2,%3}, {%4,%5,%6,%7}, {%8,%9}, {%0,%1,%2,%3};"
                        : "+f"(cL[mt][0]), "+f"(cL[mt][1]),
                          "+f"(cL[mt][2]), "+f"(cL[mt][3])
                        : "r"(a[mt][0]), "r"(a[mt][1]), "r"(a[mt][2]), "r"(a[mt][3]),
                          "r"(bl0), "r"(bl1));
                }
            }
        }
        __syncthreads();
    }

    // epilogue: h1b bf16 only + logits (warpN==0)
#pragma unroll
    for (int mt = 0; mt < 2; mt++) {
        int row = m0 + warpM * 32 + mt * 16 + g;
#pragma unroll
        for (int nt = 0; nt < 8; nt++) {
            int col = warpN * 64 + nt * 8 + t * 2;
            if (row < n)
                *(__nv_bfloat162*)&g_h1b[(size_t)row * 128 + col] =
                    __floats2bfloat162_rn(c[mt][nt][0], c[mt][nt][1]);
            if (row + 8 < n)
                *(__nv_bfloat162*)&g_h1b[(size_t)(row + 8) * 128 + col] =
                    __floats2bfloat162_rn(c[mt][nt][2], c[mt][nt][3]);
        }
    }
    if (warpN == 0) {
#pragma unroll
        for (int mt = 0; mt < 2; mt++) {
            int row = m0 + warpM * 32 + mt * 16 + g;
            float v0 = cL[mt][0], v1 = cL[mt][1];   // cols 2t, 2t+1 (row)
            float u0 = cL[mt][2], u1 = cL[mt][3];   // cols 2t, 2t+1 (row+8)
            float v2 = __shfl_down_sync(0xffffffffu, v0, 1);
            float v3 = __shfl_down_sync(0xffffffffu, v1, 1);
            float u2 = __shfl_down_sync(0xffffffffu, u0, 1);
            float u3 = __shfl_down_sync(0xffffffffu, u1, 1);
            if (t == 0) {
                if (row < n)     g_al1s[row]     = make_float4(v0, v1, v2, v3);
                if (row + 8 < n) g_al1s[row + 8] = make_float4(u0, u1, u2, u3);
            }
            if (t == 2) {
                if (row < n)     g_al1d[row]     = make_float4(v0, v1, v2, v3);
                if (row + 8 < n) g_al1d[row + 8] = make_float4(u0, u1, u2, u3);
            }
        }
    }
}

// ---------------- layer-1 fused aggregation (bf16 natural-layout gather) ----------------
// lane owns 4 consecutive channels of one head: cols 4*lane .. 4*lane+3, head = lane>>3
__global__ void __launch_bounds__(256) k_agg1(const float* __restrict__ b1, int n) {
    __shared__ __align__(16) float4 s_w[8][32];
    __shared__ int s_src[8][32];
    int lane = threadIdx.x & 31;
    int wib = threadIdx.x >> 5;
    int node = blockIdx.x * 8 + wib;
    if (node >= n) return;
    int head = lane >> 3;
    int degn = g_deg[node]; if (degn > BKT) degn = BKT;
    const int* bkt = g_bkt + (size_t)node * BKT;

    float4 alD = g_al1d[node];
    float4 alS = g_al1s[node];

    float w0 = __expf(lrelu(alS.x + alD.x));
    float w1 = __expf(lrelu(alS.y + alD.y));
    float w2 = __expf(lrelu(alS.z + alD.z));
    float w3 = __expf(lrelu(alS.w + alD.w));
    float t0 = (lane == 0) ? w0 : 0.f, t1 = (lane == 0) ? w1 : 0.f;
    float t2 = (lane == 0) ? w2 : 0.f, t3 = (lane == 0) ? w3 : 0.f;
    float wself = (head == 0) ? w0 : (head == 1) ? w1 : (head == 2) ? w2 : w3;

    const __nv_bfloat16* __restrict__ hp1 = g_h1b;

    // self term from bf16 row
    uint2 us = *(const uint2*)(hp1 + (size_t)node * 128 + 4 * lane);
    float2 fs01 = __bfloat1622float2(*(const __nv_bfloat162*)&us.x);
    float2 fs23 = __bfloat1622float2(*(const __nv_bfloat162*)&us.y);
    float acc0 = fs01.x * wself;
    float acc1 = fs01.y * wself;
    float acc2 = fs23.x * wself;
    float acc3 = fs23.y * wself;

    for (int chunk = 0; chunk < degn; chunk += 32) {
        int i = chunk + lane;
        float4 w = make_float4(0.f, 0.f, 0.f, 0.f);
        int s = 0;
        if (i < degn) {
            s = __ldg(&bkt[i]);
            float4 a = __ldg(&g_al1s[s]);
            w.x = __expf(lrelu(a.x + alD.x));
            w.y = __expf(lrelu(a.y + alD.y));
            w.z = __expf(lrelu(a.z + alD.z));
            w.w = __expf(lrelu(a.w + alD.w));
            t0 += w.x; t1 += w.y; t2 += w.z; t3 += w.w;
        }
        s_src[wib][lane] = s;
        s_w[wib][lane] = w;
        __syncwarp(0xffffffffu);
        int cnt = degn - chunk; if (cnt > 32) cnt = 32;
        int j = 0;
        for (; j + 4 <= cnt; j += 4) {
            int sa = s_src[wib][j    ];
            int sb = s_src[wib][j + 1];
            int sc = s_src[wib][j + 2];
            int sd = s_src[wib][j + 3];
            uint2 ua = __ldg((const uint2*)(hp1 + (size_t)sa * 128 + 4 * lane));
            uint2 ub = __ldg((const uint2*)(hp1 + (size_t)sb * 128 + 4 * lane));
            uint2 uc = __ldg((const uint2*)(hp1 + (size_t)sc * 128 + 4 * lane));
            uint2 ud = __ldg((const uint2*)(hp1 + (size_t)sd * 128 + 4 * lane));
            float4 wa = s_w[wib][j    ];
            float4 wb = s_w[wib][j + 1];
            float4 wc = s_w[wib][j + 2];
            float4 wd = s_w[wib][j + 3];
            float wsa = (head == 0) ? wa.x : (head == 1) ? wa.y : (head == 2) ? wa.z : wa.w;
            float wsb = (head == 0) ? wb.x : (head == 1) ? wb.y : (head == 2) ? wb.z : wb.w;
            float wsc = (head == 0) ? wc.x : (head == 1) ? wc.y : (head == 2) ? wc.z : wc.w;
            float wsd = (head == 0) ? wd.x : (head == 1) ? wd.y : (head == 2) ? wd.z : wd.w;
            float2 fa01 = __bfloat1622float2(*(const __nv_bfloat162*)&ua.x);
            float2 fa23 = __bfloat1622float2(*(const __nv_bfloat162*)&ua.y);
            float2 fb01 = __bfloat1622float2(*(const __nv_bfloat162*)&ub.x);
            float2 fb23 = __bfloat1622float2(*(const __nv_bfloat162*)&ub.y);
            float2 fc01 = __bfloat1622float2(*(const __nv_bfloat162*)&uc.x);
            float2 fc23 = __bfloat1622float2(*(const __nv_bfloat162*)&uc.y);
            float2 fd01 = __bfloat1622float2(*(const __nv_bfloat162*)&ud.x);
            float2 fd23 = __bfloat1622float2(*(const __nv_bfloat162*)&ud.y);
            acc0 = fmaf(fa01.x, wsa, acc0); acc1 = fmaf(fa01.y, wsa, acc1);
            acc2 = fmaf(fa23.x, wsa, acc2); acc3 = fmaf(fa23.y, wsa, acc3);
            acc0 = fmaf(fb01.x, wsb, acc0); acc1 = fmaf(fb01.y, wsb, acc1);
            acc2 = fmaf(fb23.x, wsb, acc2); acc3 = fmaf(fb23.y, wsb, acc3);
            acc0 = fmaf(fc01.x, wsc, acc0); acc1 = fmaf(fc01.y, wsc, acc1);
            acc2 = fmaf(fc23.x, wsc, acc2); acc3 = fmaf(fc23.y, wsc, acc3);
            acc0 = fmaf(fd01.x, wsd, acc0); acc1 = fmaf(fd01.y, wsd, acc1);
            acc2 = fmaf(fd23.x, wsd, acc2); acc3 = fmaf(fd23.y, wsd, acc3);
        }
        for (; j < cnt; j++) {
            int sj = s_src[wib][j];
            float4 wj = s_w[wib][j];
            float ws = (head == 0) ? wj.x : (head == 1) ? wj.y : (head == 2) ? wj.z : wj.w;
            uint2 u = __ldg((const uint2*)(hp1 + (size_t)sj * 128 + 4 * lane));
            float2 f01 = __bfloat1622float2(*(const __nv_bfloat162*)&u.x);
            float2 f23 = __bfloat1622float2(*(const __nv_bfloat162*)&u.y);
            acc0 = fmaf(f01.x, ws, acc0);
            acc1 = fmaf(f01.y, ws, acc1);
            acc2 = fmaf(f23.x, ws, acc2);
            acc3 = fmaf(f23.y, ws, acc3);
        }
        __syncwarp(0xffffffffu);
    }

#pragma unroll
    for (int o = 16; o > 0; o >>= 1) {
        t0 += __shfl_xor_sync(0xffffffffu, t0, o);
        t1 += __shfl_xor_sync(0xffffffffu, t1, o);
        t2 += __shfl_xor_sync(0xffffffffu, t2, o);
        t3 += __shfl_xor_sync(0xffffffffu, t3, o);
    }
    float tsel = (head == 0) ? t0 : (head == 1) ? t1 : (head == 2) ? t2 : t3;
    float inv = 1.f / tsel;
    float4 b1v = *(const float4*)&b1[4 * lane];
    float v0 = acc0 * inv + b1v.x;
    float v1 = acc1 * inv + b1v.y;
    float v2 = acc2 * inv + b1v.z;
    float v3 = acc3 * inv + b1v.w;
    float4 outv;
    outv.x = v0 > 0.f ? v0 : (__expf(v0) - 1.f);
    outv.y = v1 > 0.f ? v1 : (__expf(v1) - 1.f);
    outv.z = v2 > 0.f ? v2 : (__expf(v2) - 1.f);
    outv.w = v3 > 0.f ? v3 : (__expf(v3) - 1.f);
    *(float4*)&g_h1a[(size_t)node * 128 + 4 * lane] = outv;
}

// ---------------- GEMM2 (tf32) + fused layer-2 logits ----------------
__global__ void __launch_bounds__(256) k_gemm2(const float* __restrict__ B,
                                               const float* __restrict__ a_s,
                                               const float* __restrict__ a_d, int n) {
    __shared__ __align__(16) float As[128][68];
    __shared__ __align__(16) float Bs[64][36];
    int tid = threadIdx.x;
    int lane = tid & 31;
    int warp = tid >> 5;
    int g = lane >> 2;
    int t = lane & 3;
    int m0 = blockIdx.x * 128;

    float c[4][4];
#pragma unroll
    for (int nt = 0; nt < 4; nt++)
#pragma unroll
        for (int q = 0; q < 4; q++) c[nt][q] = 0.f;

    for (int k0 = 0; k0 < 128; k0 += 64) {
        {
            int r = tid >> 4;
            int c4 = (tid & 15) * 4;
#pragma unroll
            for (int p = 0; p < 8; p++) {
                int row = r + p * 16;
                int grow = m0 + row;
                float4 v = make_float4(0.f, 0.f, 0.f, 0.f);
                if (grow < n) v = *(const float4*)&g_h1a[(size_t)grow * 128 + k0 + c4];
                As[row][c4 + 0] = __uint_as_float(f2tf32(v.x));
                As[row][c4 + 1] = __uint_as_float(f2tf32(v.y));
                As[row][c4 + 2] = __uint_as_float(f2tf32(v.z));
                As[row][c4 + 3] = __uint_as_float(f2tf32(v.w));
            }
        }
        {
            int r = tid >> 3;
            int c4 = (tid & 7) * 4;
#pragma unroll
            for (int p = 0; p < 2; p++) {
                int k = r + p * 32;
                float4 v = *(const float4*)(B + (size_t)(k0 + k) * 32 + c4);
                Bs[k][c4 + 0] = __uint_as_float(f2tf32(v.x));
                Bs[k][c4 + 1] = __uint_as_float(f2tf32(v.y));
                Bs[k][c4 + 2] = __uint_as_float(f2tf32(v.z));
                Bs[k][c4 + 3] = __uint_as_float(f2tf32(v.w));
            }
        }
        __syncthreads();

#pragma unroll
        for (int ks = 0; ks < 8; ks++) {
            int kk = ks * 8;
            int r = warp * 16 + g;
            unsigned a0 = __float_as_uint(As[r    ][kk + t    ]);
            unsigned a1 = __float_as_uint(As[r + 8][kk + t    ]);
            unsigned a2 = __float_as_uint(As[r    ][kk + t + 4]);
            unsigned a3 = __float_as_uint(As[r + 8][kk + t + 4]);
#pragma unroll
            for (int nt = 0; nt < 4; nt++) {
                int cN = nt * 8 + g;
                unsigned b0 = __float_as_uint(Bs[kk + t    ][cN]);
                unsigned b1 = __float_as_uint(Bs[kk + t + 4][cN]);
                asm volatile(
                    "mma.sync.aligned.m16n8k8.row.col.f32.tf32.tf32.f32 "
                    "{%0,%1,%2,%3}, {%4,%5,%6,%7}, {%8,%9}, {%0,%1,%2,%3};"
                    : "+f"(c[nt][0]), "+f"(c[nt][1]), "+f"(c[nt][2]), "+f"(c[nt][3])
                    : "r"(a0), "r"(a1), "r"(a2), "r"(a3), "r"(b0), "r"(b1));
            }
        }
        __syncthreads();
    }

    int row = m0 + warp * 16 + g;
    float s_lo = 0.f, d_lo = 0.f, s_hi = 0.f, d_hi = 0.f;
#pragma unroll
    for (int nt = 0; nt < 4; nt++) {
        int col = nt * 8 + t * 2;
        float as0 = a_s[col], as1 = a_s[col + 1];
        float ad0 = a_d[col], ad1 = a_d[col + 1];
        s_lo = fmaf(c[nt][0], as0, fmaf(c[nt][1], as1, s_lo));
        d_lo = fmaf(c[nt][0], ad0, fmaf(c[nt][1], ad1, d_lo));
        s_hi = fmaf(c[nt][2], as0, fmaf(c[nt][3], as1, s_hi));
        d_hi = fmaf(c[nt][2], ad0, fmaf(c[nt][3], ad1, d_hi));
        if (row < n)
            *(float2*)&g_h2[(size_t)row * 32 + col] = make_float2(c[nt][0], c[nt][1]);
        if (row + 8 < n)
            *(float2*)&g_h2[(size_t)(row + 8) * 32 + col] = make_float2(c[nt][2], c[nt][3]);
    }
#pragma unroll
    for (int o = 1; o <= 2; o <<= 1) {
        s_lo += __shfl_xor_sync(0xffffffffu, s_lo, o);
        d_lo += __shfl_xor_sync(0xffffffffu, d_lo, o);
        s_hi += __shfl_xor_sync(0xffffffffu, s_hi, o);
        d_hi += __shfl_xor_sync(0xffffffffu, d_hi, o);
    }
    if (t == 0) {
        if (row < n)     { g_al2s[row]     = s_lo; g_al2d[row]     = d_lo; }
        if (row + 8 < n) { g_al2s[row + 8] = s_hi; g_al2d[row + 8] = d_hi; }
    }
}

// ---------------- layer-2 aggregation (fp32 gather from buckets) + mean-pool partial ----------------
__global__ void __launch_bounds__(256) k_agg2(int n) {
    __shared__ __align__(16) float s_w2[8][32];
    __shared__ int s_src2[8][32];
    __shared__ __align__(16) float bacc[8][32];
    int tid = threadIdx.x;
    int lane = tid & 31;
    int wib = tid >> 5;
    int node = blockIdx.x * 8 + wib;

    float acc = 0.f;
    if (node < n) {
        int degn = g_deg[node]; if (degn > BKT) degn = BKT;
        const int* bkt = g_bkt + (size_t)node * BKT;
        float alD = g_al2d[node];
        float ws = __expf(lrelu(g_al2s[node] + alD));
        float t = (lane == 0) ? ws : 0.f;
        acc = g_h2[(size_t)node * 32 + lane] * ws;

        for (int chunk = 0; chunk < degn; chunk += 32) {
            int i = chunk + lane;
            float w = 0.f;
            int s = 0;
            if (i < degn) {
                s = __ldg(&bkt[i]);
                w = __expf(lrelu(__ldg(&g_al2s[s]) + alD));
                t += w;
            }
            s_src2[wib][lane] = s;
            s_w2[wib][lane] = w;
            __syncwarp(0xffffffffu);
            int cnt = degn - chunk; if (cnt > 32) cnt = 32;
#pragma unroll 2
            for (int j = 0; j < cnt; j++) {
                int sj = s_src2[wib][j];
                float wj = s_w2[wib][j];
                acc = fmaf(__ldg(&g_h2[(size_t)sj * 32 + lane]), wj, acc);
            }
            __syncwarp(0xffffffffu);
        }
#pragma unroll
        for (int o = 16; o > 0; o >>= 1) t += __shfl_xor_sync(0xffffffffu, t, o);
        acc *= (1.f / t);
    }
    bacc[wib][lane] = acc;
    __syncthreads();
    if (tid < 32) {
        float s = 0.f;
#pragma unroll
        for (int w = 0; w < 8; w++) s += bacc[w][tid];
        atomicAdd(&g_pool[tid], s);
    }
}

// ---------------- final: pooled mean -> linear -> softmax ----------------
__global__ void k_final(const float* __restrict__ linW, const float* __restrict__ linb,
                        const float* __restrict__ b2, float* __restrict__ out, int n) {
    if (threadIdx.x == 0) {
        float p[32];
        float invn = 1.f / (float)n;
        for (int c = 0; c < 32; c++) p[c] = g_pool[c] * invn + b2[c];
        float lg[3];
        for (int j = 0; j < 3; j++) lg[j] = linb[j];
        for (int c = 0; c < 32; c++)
            for (int j = 0; j < 3; j++) lg[j] += p[c] * linW[c * 3 + j];
        float mx = fmaxf(lg[0], fmaxf(lg[1], lg[2]));
        float e0 = expf(lg[0] - mx), e1 = expf(lg[1] - mx), e2 = expf(lg[2] - mx);
        float s = e0 + e1 + e2;
        out[0] = e0 / s; out[1] = e1 / s; out[2] = e2 / s;
    }
}

// ---------------- launcher (bucket build forked onto a side stream) ----------------
static cudaStream_t g_s2 = nullptr;
static cudaEvent_t  g_evFork = nullptr, g_evJoin = nullptr;

extern "C" void kernel_launch(void* const* d_in, const int* in_sizes, int n_in,
                              void* d_out, int out_size) {
    const float* x    = (const float*)d_in[0];
    const void*  ei   = d_in[1];
    const float* W1   = (const float*)d_in[2];
    const float* a1s  = (const float*)d_in[3];
    const float* a1d  = (const float*)d_in[4];
    const float* b1   = (const float*)d_in[5];
    const float* W2   = (const float*)d_in[6];
    const float* a2s  = (const float*)d_in[7];
    const float* a2d  = (const float*)d_in[8];
    const float* b2   = (const float*)d_in[9];
    const float* linW = (const float*)d_in[10];
    const float* linb = (const float*)d_in[11];
    float*       out  = (float*)d_out;

    int n = in_sizes[0] / 128;       // 100000
    int E = in_sizes[1] / 2;         // 1600000
    if (n > NMAX) n = NMAX;
    if (E > EMAX) E = EMAX;

    if (!g_s2) {
        cudaStreamCreateWithFlags(&g_s2, cudaStreamNonBlocking);
        cudaEventCreateWithFlags(&g_evFork, cudaEventDisableTiming);
        cudaEventCreateWithFlags(&g_evJoin, cudaEventDisableTiming);
    }

    // fork: bucket build on side stream, concurrent with prep+gemm1 on main stream
    cudaEventRecord(g_evFork, 0);
    cudaStreamWaitEvent(g_s2, g_evFork, 0);

    k_init <<<(n + 255) / 256, 256, 0, g_s2>>>((const unsigned long long*)ei, E, n);
    k_fill <<<(E + 255) / 256, 256, 0, g_s2>>>(ei, E);
    cudaEventRecord(g_evJoin, g_s2);

    k_prep <<<1, 128>>>(W1, a1s, a1d);
    k_gemm1<<<(n + 127) / 128, 256>>>(x, W1, n);

    // join: agg1 needs buckets + logits + h1b
    cudaStreamWaitEvent(0, g_evJoin, 0);

    k_agg1 <<<(n + 7) / 8, 256>>>(b1, n);
    k_gemm2<<<(n + 127) / 128, 256>>>(W2, a2s, a2d, n);
    k_agg2 <<<(n + 7) / 8, 256>>>(n);
    k_final<<<1, 32>>>(linW, linb, b2, out, n);
}